// round 14
// baseline (speedup 1.0000x reference)
#include <cuda_runtime.h>
#include <cstdint>

#define D 8192
#define THREADS 256
#define NWARPS (THREADS / 32)           // 8
#define NV4 (D / 4 / THREADS)           // 8 float4 per thread
#define BUF 512                         // candidate buffer
#define ROW_BYTES (D * 4)               // 32768

// ---- PTX helpers (sm_90+/sm_103a) ----
__device__ __forceinline__ uint32_t smem_u32(const void* p) {
    return (uint32_t)__cvta_generic_to_shared(p);
}
__device__ __forceinline__ void mbar_init(uint32_t mbar, uint32_t count) {
    asm volatile("mbarrier.init.shared::cta.b64 [%0], %1;" :: "r"(mbar), "r"(count) : "memory");
}
__device__ __forceinline__ void mbar_expect_tx(uint32_t mbar, uint32_t bytes) {
    asm volatile("mbarrier.arrive.expect_tx.shared::cta.b64 _, [%0], %1;"
                 :: "r"(mbar), "r"(bytes) : "memory");
}
__device__ __forceinline__ void tma_1d_g2s(uint32_t dst_smem, const void* src_gmem,
                                           uint32_t bytes, uint32_t mbar) {
    asm volatile("cp.async.bulk.shared::cluster.global.mbarrier::complete_tx::bytes "
                 "[%0], [%1], %2, [%3];"
                 :: "r"(dst_smem), "l"(src_gmem), "r"(bytes), "r"(mbar) : "memory");
}
__device__ __forceinline__ void mbar_wait(uint32_t mbar, uint32_t parity) {
    uint32_t done;
    asm volatile("{\n\t.reg .pred p;\n\t"
                 "mbarrier.try_wait.parity.acquire.cta.shared::cta.b64 p, [%1], %2;\n\t"
                 "selp.b32 %0, 1, 0, p;\n\t}"
                 : "=r"(done) : "r"(mbar), "r"(parity) : "memory");
    if (!done) {
        asm volatile("{\n\t.reg .pred P1;\n"
                     "WL_%=:\n\t"
                     "mbarrier.try_wait.parity.acquire.cta.shared::cta.b64 P1, [%0], %1, 0x989680;\n\t"
                     "@P1 bra.uni WD_%=;\n\t"
                     "bra.uni WL_%=;\n"
                     "WD_%=:\n\t}"
                     :: "r"(mbar), "r"(parity) : "memory");
    }
}

extern __shared__ float srow[];          // dynamic: D floats = 32 KB (single buffer)

// Read-only sparsemax: out pre-zeroed by memset node. Streams rows via TMA
// (6 CTAs/SM), computes tau, scatters ONLY the support. The row buffer is
// fully consumed at the gather barrier, so the next row's TMA is issued
// there — Michelot + scatter (warp 0 only) overlap the next load.
__global__ __launch_bounds__(THREADS, 6)
void sparsemax_kernel(const float* __restrict__ x, float* __restrict__ out, int nrows) {
    __shared__ float sbuf[BUF];          // candidate values
    __shared__ int   sidx[BUF];          // candidate column indices
    __shared__ float swarp[NWARPS];      // block max scratch
    __shared__ float sredf[NWARPS];      // fallback sum scratch
    __shared__ int   sredk[NWARPS];      // fallback count scratch
    __shared__ int   s_cnt;
    __shared__ float s_tau;              // fallback only
    __shared__ int   s_k;                // fallback only
    __shared__ __align__(8) uint64_t mbar_storage;

    const int tid = threadIdx.x;
    const int lid = tid & 31;
    const int stride = gridDim.x;
    int r = blockIdx.x;
    if (r >= nrows) return;

    const uint32_t mb = smem_u32(&mbar_storage);
    const uint32_t ba = smem_u32(&srow[0]);
    const float4* __restrict__ sp4 = reinterpret_cast<const float4*>(srow);

    if (tid == 0) {
        mbar_init(mb, 1);
        s_cnt = 0;
        asm volatile("fence.mbarrier_init.release.cluster;" ::: "memory");
    }
    __syncthreads();

    // ---- prologue: TMA first row ----
    if (tid == 0) {
        mbar_expect_tx(mb, ROW_BYTES);
        tma_1d_g2s(ba, x + (size_t)r * D, ROW_BYTES, mb);
    }

    uint32_t ph = 0u;

    while (true) {
        mbar_wait(mb, ph); ph ^= 1u;

        // ---- PASS A: per-thread max over this thread's 32 elements ----
        float m_local;
        {
            float4 a0 = sp4[tid];
            float4 a1 = sp4[tid + THREADS];
            float4 a2 = sp4[tid + 2 * THREADS];
            float4 a3 = sp4[tid + 3 * THREADS];
            m_local = fmaxf(fmaxf(fmaxf(a0.x, a0.y), fmaxf(a0.z, a0.w)),
                            fmaxf(fmaxf(a1.x, a1.y), fmaxf(a1.z, a1.w)));
            m_local = fmaxf(m_local, fmaxf(fmaxf(a2.x, a2.y), fmaxf(a2.z, a2.w)));
            m_local = fmaxf(m_local, fmaxf(fmaxf(a3.x, a3.y), fmaxf(a3.z, a3.w)));
        }
        {
            float4 a0 = sp4[tid + 4 * THREADS];
            float4 a1 = sp4[tid + 5 * THREADS];
            float4 a2 = sp4[tid + 6 * THREADS];
            float4 a3 = sp4[tid + 7 * THREADS];
            m_local = fmaxf(m_local, fmaxf(fmaxf(a0.x, a0.y), fmaxf(a0.z, a0.w)));
            m_local = fmaxf(m_local, fmaxf(fmaxf(a1.x, a1.y), fmaxf(a1.z, a1.w)));
            m_local = fmaxf(m_local, fmaxf(fmaxf(a2.x, a2.y), fmaxf(a2.z, a2.w)));
            m_local = fmaxf(m_local, fmaxf(fmaxf(a3.x, a3.y), fmaxf(a3.z, a3.w)));
        }

        float m = m_local;
        #pragma unroll
        for (int o = 16; o > 0; o >>= 1)
            m = fmaxf(m, __shfl_xor_sync(0xffffffffu, m, o));
        if (lid == 0) swarp[tid >> 5] = m;
        __syncthreads();                 // BARRIER 1

        float mm = swarp[lid & (NWARPS - 1)];
        #pragma unroll
        for (int o = NWARPS / 2; o > 0; o >>= 1)
            mm = fmaxf(mm, __shfl_xor_sync(0xffffffffu, mm, o));
        const float thr = mm - 1.0f;     // valid lower bound on tau*

        // ---- PASS B: gather (value, column) of candidates (guarded) ----
        if (m_local > thr) {
            #pragma unroll
            for (int i = 0; i < NV4; i++) {
                float4 v = sp4[tid + i * THREADS];
                int base = 4 * (tid + i * THREADS);
                #define GATHER1(u, off) do { if ((u) > thr) { \
                    int _p = atomicAdd(&s_cnt, 1); \
                    if (_p < BUF) { sbuf[_p] = (u); sidx[_p] = base + (off); } } } while (0)
                GATHER1(v.x, 0); GATHER1(v.y, 1); GATHER1(v.z, 2); GATHER1(v.w, 3);
                #undef GATHER1
            }
        }
        __syncthreads();                 // BARRIER 2: row buffer fully consumed
        const int cnt = s_cnt;
        const int rn = r + stride;
        const bool has_next = (rn < nrows);

        if (cnt <= BUF) {
            // ---- EARLY RELOAD: next row streams in under Michelot+scatter ----
            if (tid == 0 && has_next) {
                mbar_expect_tx(mb, ROW_BYTES);
                tma_1d_g2s(ba, x + (size_t)rn * D, ROW_BYTES, mb);
            }
            // ---- warp 0 alone: Michelot + sparse scatter; others go wait ----
            if (tid < 32) {
                float tau = thr;
                int prev = -1;
                for (int it = 0; it < cnt + 2; it++) {
                    float s = 0.0f; int k = 0;
                    for (int j = lid; j < cnt; j += 32) {
                        float v = sbuf[j];
                        if (v > tau) { s += v; k++; }
                    }
                    #pragma unroll
                    for (int o = 16; o > 0; o >>= 1) {
                        s += __shfl_xor_sync(0xffffffffu, s, o);
                        k += __shfl_xor_sync(0xffffffffu, k, o);
                    }
                    tau = (s - 1.0f) / (float)k;
                    if (k == prev) break;   // active set stable -> fixed point
                    prev = k;
                }
                // scatter support (out pre-zeroed); candidates <= tau stay 0
                float* __restrict__ orow = out + (size_t)r * D;
                for (int j = lid; j < cnt; j += 32) {
                    float v = sbuf[j];
                    if (v > tau) orow[sidx[j]] = v - tau;
                }
                if (lid == 0) s_cnt = 0;   // before warp0 reaches next BARRIER 1
            }
        } else {
            // ---- Fallback (adversarial inputs): block Michelot + full store ----
            float tau = thr;
            int prev = -1;
            for (int it = 0; it < D + 2; it++) {
                float s = 0.0f; int k = 0;
                #pragma unroll
                for (int i = 0; i < NV4; i++) {
                    float4 v = sp4[tid + i * THREADS];
                    #define ACC(u) do { if ((u) > tau) { s += (u); k++; } } while (0)
                    ACC(v.x); ACC(v.y); ACC(v.z); ACC(v.w);
                    #undef ACC
                }
                #pragma unroll
                for (int o = 16; o > 0; o >>= 1) {
                    s += __shfl_xor_sync(0xffffffffu, s, o);
                    k += __shfl_xor_sync(0xffffffffu, k, o);
                }
                if (lid == 0) { sredf[tid >> 5] = s; sredk[tid >> 5] = k; }
                __syncthreads();
                if (tid == 0) {
                    float S = 0.0f; int K = 0;
                    #pragma unroll
                    for (int w = 0; w < NWARPS; w++) { S += sredf[w]; K += sredk[w]; }
                    s_tau = (S - 1.0f) / (float)K;
                    s_k = K;
                }
                __syncthreads();
                tau = s_tau;
                int K = s_k;
                if (K == prev) break;
                prev = K;
            }
            // full dense store (correct regardless of pre-zeroing)
            float4* __restrict__ xout = reinterpret_cast<float4*>(out + (size_t)r * D);
            #pragma unroll
            for (int i = 0; i < NV4; i++) {
                float4 v = sp4[tid + i * THREADS];
                v.x = fmaxf(v.x - tau, 0.0f);
                v.y = fmaxf(v.y - tau, 0.0f);
                v.z = fmaxf(v.z - tau, 0.0f);
                v.w = fmaxf(v.w - tau, 0.0f);
                __stcs(&xout[tid + i * THREADS], v);
            }
            __syncthreads();             // buffer consumed
            if (tid == 0) {
                s_cnt = 0;
                if (has_next) {
                    mbar_expect_tx(mb, ROW_BYTES);
                    tma_1d_g2s(ba, x + (size_t)rn * D, ROW_BYTES, mb);
                }
            }
        }

        if (!has_next) break;
        r = rn;
    }
}

extern "C" void kernel_launch(void* const* d_in, const int* in_sizes, int n_in,
                              void* d_out, int out_size) {
    const float* x = (const float*)d_in[0];
    float* out = (float*)d_out;
    const int rows = in_sizes[0] / D;   // 8192

    const int dyn_smem = D * (int)sizeof(float);   // 32 KB single buffer
    cudaFuncSetAttribute(sparsemax_kernel,
                         cudaFuncAttributeMaxDynamicSharedMemorySize, dyn_smem);

    int dev = 0;
    cudaGetDevice(&dev);
    int nsm = 148;
    cudaDeviceGetAttribute(&nsm, cudaDevAttrMultiProcessorCount, dev);
    int grid = nsm * 6;                 // 6 CTAs/SM: max independent row streams
    if (grid > rows) grid = rows;

    // 1) zero output at dedicated write bandwidth (graph-capturable memset node)
    cudaMemsetAsync(d_out, 0, (size_t)out_size * sizeof(float));
    // 2) read-paced sparsemax: scatters support only, overlapped Michelot/reload
    sparsemax_kernel<<<grid, THREADS, dyn_smem>>>(x, out, rows);
}